// round 16
// baseline (speedup 1.0000x reference)
#include <cuda_runtime.h>
#include <cuda_fp16.h>
#include <math.h>
#include <float.h>
#include <stdint.h>

// ---------------- problem constants ----------------
#define BB   2
#define T0C  1024
#define TOTC 2048
#define DC   2048
#define NC   16
#define KC   8
#define HC   128
#define FC   8192
#define NHC  2048   // N*H
#define KHC  1024   // K*H
#define GC   2      // N/K

typedef __half fp16;

// ---------------- helpers ----------------
__device__ __forceinline__ uint32_t smem_to_u32(const void* p) {
    uint32_t a;
    asm("{ .reg .u64 t; cvta.to.shared.u64 t, %1; cvt.u32.u64 %0, t; }" : "=r"(a) : "l"(p));
    return a;
}
#define LDSM4(r, addr) \
    asm volatile("ldmatrix.sync.aligned.m8n8.x4.shared.b16 {%0,%1,%2,%3}, [%4];" \
        : "=r"((r)[0]), "=r"((r)[1]), "=r"((r)[2]), "=r"((r)[3]) : "r"(addr))
#define LDSM4T(r, addr) \
    asm volatile("ldmatrix.sync.aligned.m8n8.x4.trans.shared.b16 {%0,%1,%2,%3}, [%4];" \
        : "=r"((r)[0]), "=r"((r)[1]), "=r"((r)[2]), "=r"((r)[3]) : "r"(addr))
#define MMAF16(d, a, b0, b1) \
    asm volatile("mma.sync.aligned.m16n8k16.row.col.f32.f16.f16.f32 " \
        "{%0,%1,%2,%3},{%4,%5,%6,%7},{%8,%9},{%0,%1,%2,%3};" \
        : "+f"((d)[0]), "+f"((d)[1]), "+f"((d)[2]), "+f"((d)[3]) \
        : "r"((a)[0]), "r"((a)[1]), "r"((a)[2]), "r"((a)[3]), "r"(b0), "r"(b1))
#define CP_ASYNC16(saddr, gaddr) \
    asm volatile("cp.async.cg.shared.global [%0], [%1], 16;" :: "r"(saddr), "l"(gaddr))
#define CP_COMMIT() asm volatile("cp.async.commit_group;" ::: "memory")
#define CP_WAIT(n)  asm volatile("cp.async.wait_group %0;" :: "n"(n) : "memory")

#define MBAR_WAIT(bar, ph) do { \
    uint32_t _done; \
    asm volatile("{\n\t.reg .pred p;\n\t" \
        "mbarrier.try_wait.parity.acquire.cta.shared::cta.b64 p, [%1], %2;\n\t" \
        "selp.b32 %0, 1, 0, p;\n\t}" : "=r"(_done) : "r"(bar), "r"(ph) : "memory"); \
    while (!_done) { \
        asm volatile("{\n\t.reg .pred p;\n\t" \
            "mbarrier.try_wait.parity.acquire.cta.shared::cta.b64 p, [%1], %2;\n\t" \
            "selp.b32 %0, 1, 0, p;\n\t}" : "=r"(_done) : "r"(bar), "r"(ph) : "memory"); \
    } \
} while (0)

// ---------------- blocked-layout index helpers ----------------
// A-blocks: 256 rows x 32 cols, padded row = 40 elems (80 B) -> 10240 elems/block
// W-blocks: 128 rows x 32 cols, padded row = 40 elems (80 B) ->  5120 elems/block
__device__ __forceinline__ size_t ablk2048(size_t row, int col) {
    return ((row >> 8) * 64 + (size_t)(col >> 5)) * 10240
         + (row & 255) * 40 + (size_t)((((col & 31) >> 3) << 3) + (col & 7));
}
__device__ __forceinline__ size_t ablk8192(size_t row, int col) {
    return ((row >> 8) * 256 + (size_t)(col >> 5)) * 10240
         + (row & 255) * 40 + (size_t)((((col & 31) >> 3) << 3) + (col & 7));
}

// ---------------- scratch (device globals; no runtime alloc) ----------------
__device__ float g_res [(size_t)BB*TOTC*DC];

__device__ fp16 g_qkvh[(size_t)BB*TOTC*4096];    // linear (feeds rope only)
__device__ fp16 g_q   [(size_t)BB*TOTC*NHC];
__device__ fp16 g_k   [(size_t)BB*TOTC*KHC];
__device__ fp16 g_v   [(size_t)BB*TOTC*KHC];
__device__ fp16 g_pre [10485760];   // blocked, Kd=2048
__device__ fp16 g_enc [10485760];   // blocked, Kd=2048
__device__ fp16 g_hid [10485760];   // blocked, Kd=2048
__device__ fp16 g_gu  [41943040];   // blocked, Kd=8192
__device__ fp16 g_wf  [157286400];  // blocked weights

// ---------------- elementwise helpers ----------------
__device__ __forceinline__ float gelu_tanh(float x) {
    float x3 = x * x * x;
    return 0.5f * x * (1.0f + tanhf(0.7978845608028654f * (x + 0.044715f * x3)));
}
__device__ __forceinline__ uint32_t pack2h(float a, float b) {
    __half2 h = __floats2half2_rn(a, b);
    return *(uint32_t*)&h;
}

// ---------------- weight conversion: fp16, blocked layout, 14 jobs ----------------
#define NJOBS 14
struct CvtF16Jobs {
    const float* src[NJOBS];
    fp16* dst[NJOBS];      // blocked weight base
    int lk[NJOBS];         // log2(Kd)
    int rowbase[NJOBS];
    int ilv[NJOBS];        // 0 none, 1 even rows (2r), 2 odd rows (2r+1)
    int startblk[NJOBS + 1];
};

// 256 threads x 32 elems = 8192 source elems/block
__global__ void cvt_f16_kernel(CvtF16Jobs J)
{
    int bid = blockIdx.x;
    int j = 0;
    #pragma unroll
    for (int t = 1; t < NJOBS; ++t) if (bid >= J.startblk[t]) j = t;
    int blk_off = (bid - J.startblk[j]) * 8192;
    const float* src = J.src[j];
    fp16* dst = J.dst[j];
    const int lk = J.lk[j];
    const int Kdm = (1 << lk) - 1;
    const int nkc = 1 << (lk - 5);
    const int rowbase = J.rowbase[j];
    const int ilv = J.ilv[j];

    float4 va[4][2];
    int idx[4];
    #pragma unroll
    for (int u = 0; u < 4; ++u) {
        idx[u] = blk_off + (u * 256 + threadIdx.x) * 8;
        va[u][0] = *(const float4*)(src + idx[u]);
        va[u][1] = *(const float4*)(src + idx[u] + 4);
    }
    #pragma unroll
    for (int u = 0; u < 4; ++u) {
        uint4 o;
        o.x = pack2h(va[u][0].x, va[u][0].y);
        o.y = pack2h(va[u][0].z, va[u][0].w);
        o.z = pack2h(va[u][1].x, va[u][1].y);
        o.w = pack2h(va[u][1].z, va[u][1].w);
        int srow = idx[u] >> lk;
        int row = rowbase + (ilv ? 2 * srow + (ilv - 1) : srow);
        int col = idx[u] & Kdm;
        size_t di = ((size_t)(row >> 7) * nkc + (size_t)(col >> 5)) * 5120
                  + (size_t)(row & 127) * 40 + (size_t)(((col & 31) >> 3) << 3);
        *(uint4*)(dst + di) = o;
    }
}

// ---------------- rmsnorm pair -> fp16 blocked ----------------
// srcmode 0: src per-stream (s0/s1, rows b*T0+t); srcmode 1: concat src s0
__global__ void rmsnorm2_f16_kernel(const float* __restrict__ s0, const float* __restrict__ s1,
                                    fp16* __restrict__ dst,
                                    const float* __restrict__ sc0, const float* __restrict__ sc1,
                                    int srcmode)
{
    int istream = blockIdx.y;
    int row = blockIdx.x;
    int b = row / T0C, t = row % T0C;
    size_t crow = (size_t)b * TOTC + (size_t)istream * T0C + t;
    const float* base = istream ? s1 : s0;
    const float* scale = istream ? sc1 : sc0;
    const float* s = srcmode ? (s0 + crow * DC) : (base + (size_t)row * DC);

    __shared__ float red[256];
    float ss = 0.f;
    for (int d = threadIdx.x; d < DC; d += 256) { float v = s[d]; ss += v * v; }
    red[threadIdx.x] = ss;
    __syncthreads();
    for (int st = 128; st > 0; st >>= 1) {
        if (threadIdx.x < st) red[threadIdx.x] += red[threadIdx.x + st];
        __syncthreads();
    }
    float inv = rsqrtf(red[0] * (1.0f / DC) + 1e-6f);
    for (int d = threadIdx.x; d < DC; d += 256) {
        float v = s[d] * inv * (1.0f + scale[d]);
        dst[ablk2048(crow, d)] = __float2half_rn(v);
    }
}

// ---------------- rope + convert (fp16 qkvh linear -> fp16 q,k,v linear) ----------------
__global__ void rope_split_kernel(const fp16* __restrict__ qkv, const int* __restrict__ positions,
                                  fp16* __restrict__ q, fp16* __restrict__ k, fp16* __restrict__ v)
{
    int row = blockIdx.x;
    float pos = (float)positions[row];
    const float QSCALE = 0.08838834764831845f;
    const fp16* src = qkv + (size_t)row * 4096;

    __shared__ float ssn[64], scs[64];
    if (threadIdx.x < 64) {
        int j = threadIdx.x;
        float ts = powf(10000.0f, (float)j * (1.0f / 64.0f));
        float sn, cs;
        sincosf(pos / ts, &sn, &cs);
        ssn[j] = sn; scs[j] = cs;
    }
    __syncthreads();

    for (int w = threadIdx.x; w < (NC + KC) * 64; w += 256) {
        int head = w >> 6;
        int j = w & 63;
        float sn = ssn[j], cs = scs[j];
        if (head < NC) {
            float x1 = __half2float(src[head * HC + j]);
            float x2 = __half2float(src[head * HC + j + 64]);
            size_t o = ((size_t)row * NC + head) * HC;
            q[o + j]      = __float2half_rn((x1 * cs - x2 * sn) * QSCALE);
            q[o + j + 64] = __float2half_rn((x2 * cs + x1 * sn) * QSCALE);
        } else {
            int kkh = head - NC;
            float x1 = __half2float(src[2048 + kkh * HC + j]);
            float x2 = __half2float(src[2048 + kkh * HC + j + 64]);
            size_t o = ((size_t)row * KC + kkh) * HC;
            k[o + j]      = __float2half_rn(x1 * cs - x2 * sn);
            k[o + j + 64] = __float2half_rn(x2 * cs + x1 * sn);
        }
    }
    for (int idx = threadIdx.x; idx < KHC; idx += 256) {
        size_t o = (size_t)row * KHC + idx;
        v[o] = src[3072 + idx];
    }
}

// ---------------- GEMM geometry ----------------
#define GBM 256
#define GBN 128
#define GBK 32
#define GSTAGES 5
#define ROWB   80
#define TILEA_B (256 * ROWB)                 // 20480 bytes
#define TILEW_B (128 * ROWB)                 // 10240 bytes
#define STAGE_F (TILEA_B + TILEW_B)          // 30720
#define TC_SMEM_F (GSTAGES * STAGE_F + 64)   // + mbarrier array

// ---------------- fp16 GEMM, bulk-copy pipeline (all projections) ----------------
// A_ blocked base (unoffset). W0/W1 blocked bases.
// epi: 2 +residual->C fp32, 3 fused gate-up -> GUblk (blocked, Kd=FC), 4 plain fp16 -> H16 linear
// resmode: 0 per-stream R (R0/R1 + b*T0*ldC), 1 concat R0 (+ arow0*ldC)
// outmode: 0 concat rows, 1 stream-major rows
__global__ __launch_bounds__(512, 1)
void gemm_f16(const fp16* __restrict__ A_,
              const fp16* __restrict__ W0, const fp16* __restrict__ W1,
              float* __restrict__ C_, int Kd, int ldC, int epi,
              const float* __restrict__ R0, const float* __restrict__ R1,
              int resmode, int outmode,
              fp16* __restrict__ H16_)
{
    extern __shared__ char smem[];
    const uint32_t s0 = smem_to_u32(smem);
    const uint32_t mb = s0 + GSTAGES * STAGE_F;

    const int tid = threadIdx.x;
    const int lane = tid & 31, warp = tid >> 5;
    const int wm = warp >> 2, wn = warp & 3;      // warp tile 64(m) x 32(n)

    const int z = blockIdx.z, i = z >> 1, b = z & 1;
    const size_t arow0 = (size_t)b * TOTC + (size_t)i * T0C;
    float* C = (outmode == 0) ? (C_ + arow0 * (size_t)ldC)
                              : (C_ + ((size_t)i * BB * T0C + (size_t)b * T0C) * (size_t)ldC);
    const float* R = 0;
    if (epi == 2) R = (resmode == 0) ? ((i ? R1 : R0) + (size_t)b * T0C * ldC)
                                     : (R0 + arow0 * (size_t)ldC);
    fp16* H16 = 0;
    if (epi == 4) H16 = H16_ + arow0 * (size_t)ldC;

    const int m0 = blockIdx.y * GBM, n0 = blockIdx.x * GBN;
    const int nk = Kd / GBK;
    const fp16* Asrc = A_ + ((arow0 + (size_t)m0) >> 8) * (size_t)nk * 10240;
    const fp16* Wsrc = (i ? W1 : W0) + (size_t)(n0 >> 7) * (size_t)nk * 5120;

    if (tid == 0) {
        #pragma unroll
        for (int s = 0; s < GSTAGES; ++s)
            asm volatile("mbarrier.init.shared.b64 [%0], 1;" :: "r"(mb + s * 8) : "memory");
    }
    __syncthreads();

    #define ISSUE_B(cc) do {                                                         \
        int s_ = (cc) % GSTAGES;                                                     \
        uint32_t bar_ = mb + s_ * 8;                                                 \
        uint32_t sd_ = s0 + s_ * STAGE_F;                                            \
        const fp16* a_ = Asrc + (size_t)(cc) * 10240;                                \
        const fp16* w_ = Wsrc + (size_t)(cc) * 5120;                                 \
        asm volatile("mbarrier.arrive.expect_tx.shared.b64 _, [%0], %1;"             \
            :: "r"(bar_), "r"(30720u) : "memory");                                   \
        asm volatile("cp.async.bulk.shared::cta.global.mbarrier::complete_tx::bytes " \
            "[%0], [%1], %2, [%3];"                                                  \
            :: "r"(sd_), "l"(a_), "r"(20480u), "r"(bar_) : "memory");                \
        asm volatile("cp.async.bulk.shared::cta.global.mbarrier::complete_tx::bytes " \
            "[%0], [%1], %2, [%3];"                                                  \
            :: "r"(sd_ + 20480u), "l"(w_), "r"(10240u), "r"(bar_) : "memory");       \
    } while (0)

    if (tid == 0) { ISSUE_B(0); ISSUE_B(1); ISSUE_B(2); ISSUE_B(3); }

    float acc[4][4][4];
    #pragma unroll
    for (int mf = 0; mf < 4; ++mf)
        #pragma unroll
        for (int nf = 0; nf < 4; ++nf)
            #pragma unroll
            for (int r = 0; r < 4; ++r) acc[mf][nf][r] = 0.f;

    const int a_row = wm * 64 + (lane & 15);
    const int a_cj  = lane >> 4;
    const int b_row = wn * 32 + (lane & 7) + ((lane >> 4) & 1) * 8;
    const int b_cj  = (lane >> 3) & 1;

    for (int c = 0; c < nk; ++c) {
        MBAR_WAIT(mb + (c % GSTAGES) * 8, (uint32_t)((c / GSTAGES) & 1));
        __syncthreads();
        if (tid == 0 && c + 4 < nk) ISSUE_B(c + 4);

        uint32_t sbase = s0 + (c % GSTAGES) * STAGE_F;
        uint32_t aB = sbase, bB = sbase + TILEA_B;

        #pragma unroll
        for (int ks = 0; ks < 2; ++ks) {
            uint32_t aoff = (uint32_t)(a_row * ROWB + (ks * 2 + a_cj) * 16);
            uint32_t boff = (uint32_t)(b_row * ROWB + (ks * 2 + b_cj) * 16);

            uint32_t ah[4][4], bh[2][4];
            #pragma unroll
            for (int mf = 0; mf < 4; ++mf) LDSM4(ah[mf], aB + aoff + mf * (16 * ROWB));
            #pragma unroll
            for (int nf2 = 0; nf2 < 2; ++nf2) LDSM4(bh[nf2], bB + boff + nf2 * (16 * ROWB));

            #pragma unroll
            for (int nf2 = 0; nf2 < 2; ++nf2)
                #pragma unroll
                for (int mf = 0; mf < 4; ++mf) {
                    MMAF16(acc[mf][nf2 * 2],     ah[mf], bh[nf2][0], bh[nf2][1]);
                    MMAF16(acc[mf][nf2 * 2 + 1], ah[mf], bh[nf2][2], bh[nf2][3]);
                }
        }
    }

    #pragma unroll
    for (int mf = 0; mf < 4; ++mf) {
        int r0 = m0 + wm * 64 + mf * 16 + (lane >> 2);
        #pragma unroll
        for (int nf = 0; nf < 4; ++nf) {
            int col = n0 + wn * 32 + nf * 8 + (lane & 3) * 2;
            float2 v0 = make_float2(acc[mf][nf][0], acc[mf][nf][1]);
            float2 v1 = make_float2(acc[mf][nf][2], acc[mf][nf][3]);
            if (epi == 3) {
                int gcol = col >> 1;
                H16_[ablk8192(arow0 + (size_t)r0, gcol)]       = __float2half_rn(gelu_tanh(v0.x) * v0.y);
                H16_[ablk8192(arow0 + (size_t)(r0 + 8), gcol)] = __float2half_rn(gelu_tanh(v1.x) * v1.y);
            } else if (epi == 4) {
                *(uint32_t*)((char*)H16 + ((size_t)r0 * ldC + col) * 2)       = pack2h(v0.x, v0.y);
                *(uint32_t*)((char*)H16 + ((size_t)(r0 + 8) * ldC + col) * 2) = pack2h(v1.x, v1.y);
            } else {
                if (epi == 2) {
                    float2 ra = *(const float2*)(R + (size_t)r0 * ldC + col);
                    float2 rb = *(const float2*)(R + (size_t)(r0 + 8) * ldC + col);
                    v0.x += ra.x; v0.y += ra.y;
                    v1.x += rb.x; v1.y += rb.y;
                }
                *(float2*)(C + (size_t)r0 * ldC + col)       = v0;
                *(float2*)(C + (size_t)(r0 + 8) * ldC + col) = v1;
            }
        }
    }
}

// ---------------- attention: single-fp16 flash kernel ----------------
#define ATT_BM 128
#define ATT_BN 32
#define QROWB 272
#define KROWB 272
#define PROWB 80
#define SQ 0
#define SKV 34816
#define KVTILE 8704
#define SP 69632
#define ATT_SMEM 79872
#define NEGA (-1e30f)

__global__ __launch_bounds__(256, 1)
void attn_mma_kernel(const fp16* __restrict__ q, const fp16* __restrict__ k,
                     const fp16* __restrict__ v, fp16* __restrict__ enc)
{
    extern __shared__ char smem[];
    const uint32_t s0u = smem_to_u32(smem);
    const int tid = threadIdx.x, lane = tid & 31, w = tid >> 5;
    const int bq = blockIdx.z;
    const int n = blockIdx.y;
    const int kk = n >> 1;
    const int t0 = ((int)gridDim.x - 1 - (int)blockIdx.x) * ATT_BM;
    const size_t bT = (size_t)bq * TOTC;

    #pragma unroll
    for (int it = 0; it < 8; ++it) {
        int idx = tid + it * 256;
        int row = idx >> 4, ch = idx & 15;
        const fp16* src = q + ((bT + t0 + row) * NC + n) * HC + ch * 8;
        CP_ASYNC16(s0u + SQ + row * QROWB + ch * 16, src);
    }
    CP_COMMIT();

    #define LOAD_KV(j) do {                                                        \
        int _bf = (j) & 1; int _s0 = (j) * ATT_BN;                                 \
        _Pragma("unroll")                                                          \
        for (int it = 0; it < 4; ++it) {                                           \
            int idx = tid + it * 256;                                              \
            int tt = idx >> 9, cid = idx & 511, row = cid >> 4, ch = cid & 15;     \
            const fp16* srcp = (tt ? v : k) + ((bT + _s0 + row) * KC + kk) * HC + ch * 8; \
            CP_ASYNC16(s0u + SKV + (_bf * 2 + tt) * KVTILE + row * KROWB + ch * 16, srcp); \
        }                                                                          \
        CP_COMMIT();                                                               \
    } while (0)

    const int nb = t0 / ATT_BN + 4;
    LOAD_KV(0);

    const int tw = t0 + w * 16;
    const int r0 = lane >> 2;
    float oacc[16][4];
    #pragma unroll
    for (int a = 0; a < 16; ++a) { oacc[a][0] = oacc[a][1] = oacc[a][2] = oacc[a][3] = 0.f; }
    float mrow0 = NEGA, mrow1 = NEGA, lrow0 = 0.f, lrow1 = 0.f;

    const uint32_t ps_base = s0u + SP + (w * 16) * PROWB;

    for (int j = 0; j < nb; ++j) {
        CP_WAIT(0);
        __syncthreads();
        if (j + 1 < nb) LOAD_KV(j + 1);

        const int sblk = j * ATT_BN;
        const int bf = j & 1;
        const uint32_t kB = s0u + SKV + (bf * 2 + 0) * KVTILE;
        const uint32_t vB = s0u + SKV + (bf * 2 + 1) * KVTILE;

        if (sblk <= tw + 15) {
            float sacc[4][4];
            #pragma unroll
            for (int nf = 0; nf < 4; ++nf) { sacc[nf][0]=sacc[nf][1]=sacc[nf][2]=sacc[nf][3]=0.f; }
            const uint32_t aoff_base = (uint32_t)((w * 16 + (lane & 15)) * QROWB + (lane >> 4) * 16);
            const uint32_t brow = (uint32_t)((lane & 7) + ((lane >> 4) & 1) * 8);
            const uint32_t bco  = (uint32_t)(((lane >> 3) & 1) * 16);
            #pragma unroll
            for (int ks = 0; ks < 8; ++ks) {
                uint32_t ah[4], bh0[4], bh1[4];
                uint32_t aoff = aoff_base + ks * 32;
                LDSM4(ah, s0u + SQ + aoff);
                uint32_t boff0 = brow * KROWB + ks * 32 + bco;
                uint32_t boff1 = boff0 + 16 * KROWB;
                LDSM4(bh0, kB + boff0); LDSM4(bh1, kB + boff1);
                MMAF16(sacc[0], ah, bh0[0], bh0[1]);
                MMAF16(sacc[1], ah, bh0[2], bh0[3]);
                MMAF16(sacc[2], ah, bh1[0], bh1[1]);
                MMAF16(sacc[3], ah, bh1[2], bh1[3]);
            }

            if (sblk + ATT_BN - 1 > tw) {
                #pragma unroll
                for (int nf = 0; nf < 4; ++nf) {
                    int sg = sblk + nf * 8 + (lane & 3) * 2;
                    int tg0 = tw + r0, tg1 = tg0 + 8;
                    if (sg     > tg0) sacc[nf][0] = NEGA;
                    if (sg + 1 > tg0) sacc[nf][1] = NEGA;
                    if (sg     > tg1) sacc[nf][2] = NEGA;
                    if (sg + 1 > tg1) sacc[nf][3] = NEGA;
                }
            }

            float mx0 = NEGA, mx1 = NEGA;
            #pragma unroll
            for (int nf = 0; nf < 4; ++nf) {
                mx0 = fmaxf(mx0, fmaxf(sacc[nf][0], sacc[nf][1]));
                mx1 = fmaxf(mx1, fmaxf(sacc[nf][2], sacc[nf][3]));
            }
            mx0 = fmaxf(mx0, __shfl_xor_sync(0xffffffffu, mx0, 1));
            mx0 = fmaxf(mx0, __shfl_xor_sync(0xffffffffu, mx0, 2));
            mx1 = fmaxf(mx1, __shfl_xor_sync(0xffffffffu, mx1, 1));
            mx1 = fmaxf(mx1, __shfl_xor_sync(0xffffffffu, mx1, 2));
            float mn0 = fmaxf(mrow0, mx0), mn1 = fmaxf(mrow1, mx1);
            float al0 = __expf(mrow0 - mn0), al1 = __expf(mrow1 - mn1);
            float se0 = 0.f, se1 = 0.f;
            #pragma unroll
            for (int nf = 0; nf < 4; ++nf) {
                float p0 = __expf(sacc[nf][0] - mn0);
                float p1 = __expf(sacc[nf][1] - mn0);
                float p2 = __expf(sacc[nf][2] - mn1);
                float p3 = __expf(sacc[nf][3] - mn1);
                se0 += p0 + p1; se1 += p2 + p3;
                uint32_t pcol = (uint32_t)((nf * 8 + (lane & 3) * 2) * 2);
                *(uint32_t*)(smem + (ps_base - s0u) + r0 * PROWB + pcol)       = pack2h(p0, p1);
                *(uint32_t*)(smem + (ps_base - s0u) + (r0 + 8) * PROWB + pcol) = pack2h(p2, p3);
            }
            se0 += __shfl_xor_sync(0xffffffffu, se0, 1);
            se0 += __shfl_xor_sync(0xffffffffu, se0, 2);
            se1 += __shfl_xor_sync(0xffffffffu, se1, 1);
            se1 += __shfl_xor_sync(0xffffffffu, se1, 2);
            mrow0 = mn0; mrow1 = mn1;
            lrow0 = lrow0 * al0 + se0;
            lrow1 = lrow1 * al1 + se1;
            #pragma unroll
            for (int a = 0; a < 16; ++a) {
                oacc[a][0] *= al0; oacc[a][1] *= al0;
                oacc[a][2] *= al1; oacc[a][3] *= al1;
            }
            __syncwarp();

            const uint32_t vrow = (uint32_t)((lane & 7) + ((lane >> 3) & 1) * 8);
            const uint32_t vco  = (uint32_t)((lane >> 4) * 16);
            #pragma unroll
            for (int ks2 = 0; ks2 < 2; ++ks2) {
                uint32_t ph[4];
                uint32_t pa = (uint32_t)((lane & 15) * PROWB + (ks2 * 16 + (lane >> 4) * 8) * 2);
                LDSM4(ph, ps_base + pa);
                #pragma unroll
                for (int hf = 0; hf < 8; ++hf) {
                    uint32_t bvh[4];
                    uint32_t voff = (ks2 * 16 + vrow) * KROWB + hf * 32 + vco;
                    LDSM4T(bvh, vB + voff);
                    MMAF16(oacc[2*hf],     ph, bvh[0], bvh[1]);
                    MMAF16(oacc[2*hf + 1], ph, bvh[2], bvh[3]);
                }
            }
        }
    }

    // epilogue: normalize + store enc blocked (Kd=2048)
    float inv0 = 1.0f / lrow0, inv1 = 1.0f / lrow1;
    #pragma unroll
    for (int nt = 0; nt < 16; ++nt) {
        int hcol = nt * 8 + (lane & 3) * 2;
        int col = n * HC + hcol;
        size_t e0 = ablk2048(bT + (size_t)(tw + r0), col);
        size_t e1 = ablk2048(bT + (size_t)(tw + r0 + 8), col);
        *(uint32_t*)((char*)enc + e0 * 2) = pack2h(oacc[nt][0] * inv0, oacc[nt][1] * inv0);
        *(uint32_t*)((char*)enc + e1 * 2) = pack2h(oacc[nt][2] * inv1, oacc[nt][3] * inv1);
    }
}

// ---------------- host ----------------
extern "C" void kernel_launch(void* const* d_in, const int* in_sizes, int n_in,
                              void* d_out, int out_size)
{
    (void)in_sizes; (void)n_in; (void)out_size;
    const float* x0  = (const float*)d_in[0];
    const float* x1  = (const float*)d_in[1];
    const int*   pos = (const int*)  d_in[2];
    const float* q0w = (const float*)d_in[4];
    const float* q1w = (const float*)d_in[5];
    const float* k0w = (const float*)d_in[6];
    const float* k1w = (const float*)d_in[7];
    const float* v0w = (const float*)d_in[8];
    const float* v1w = (const float*)d_in[9];
    const float* o0w = (const float*)d_in[10];
    const float* o1w = (const float*)d_in[11];
    const float* gt0 = (const float*)d_in[12];
    const float* gt1 = (const float*)d_in[13];
    const float* up0 = (const float*)d_in[14];
    const float* up1 = (const float*)d_in[15];
    const float* dw0 = (const float*)d_in[16];
    const float* dw1 = (const float*)d_in[17];
    const float* pa0 = (const float*)d_in[18];
    const float* pa1 = (const float*)d_in[19];
    const float* pf0 = (const float*)d_in[20];
    const float* pf1 = (const float*)d_in[21];
    float* out = (float*)d_out;

    float *res;
    fp16 *qkvh, *qb, *kb, *vb, *pre, *enc, *hid, *gu, *wf;
    cudaGetSymbolAddress((void**)&res,  g_res);
    cudaGetSymbolAddress((void**)&qkvh, g_qkvh);
    cudaGetSymbolAddress((void**)&qb,   g_q);
    cudaGetSymbolAddress((void**)&kb,   g_k);
    cudaGetSymbolAddress((void**)&vb,   g_v);
    cudaGetSymbolAddress((void**)&pre,  g_pre);
    cudaGetSymbolAddress((void**)&enc,  g_enc);
    cudaGetSymbolAddress((void**)&hid,  g_hid);
    cudaGetSymbolAddress((void**)&gu,   g_gu);
    cudaGetSymbolAddress((void**)&wf,   g_wf);

    cudaFuncSetAttribute(gemm_f16, cudaFuncAttributeMaxDynamicSharedMemorySize, TC_SMEM_F);
    cudaFuncSetAttribute(attn_mma_kernel, cudaFuncAttributeMaxDynamicSharedMemorySize, ATT_SMEM);

    // blocked weight offsets (elems): block sizes include 1.25x row padding
    const size_t QKVB = 10485760;   // 4096 x 2048 blocked
    const size_t OB   = 5242880;    // 2048 x 2048 blocked
    const size_t GUB  = 41943040;   // 16384 x 2048 blocked (interleaved)
    const size_t DB   = 20971520;   // 2048 x 8192 blocked
    const size_t oqkv0 = 0, oqkv1 = QKVB;
    const size_t oo0  = 2 * QKVB,       oo1  = oo0 + OB;
    const size_t ogu0 = oo1 + OB,       ogu1 = ogu0 + GUB;
    const size_t od0  = ogu1 + GUB,     od1  = od0 + DB;
    const size_t QHALF = 5242880;       // Q rows (2048) portion of blocked qkv weight

    const size_t QN = (size_t)NHC * DC;
    const size_t KN = (size_t)KHC * DC;
    const size_t FN = (size_t)FC * DC;

    // [launch 0] all weight conversions -> fp16 blocked
    {
        CvtF16Jobs J;
        const float* srcs[NJOBS] = {q0w, k0w, v0w, q1w, k1w, v1w, o0w, o1w,
                                    gt0, up0, gt1, up1, dw0, dw1};
        const size_t offs[NJOBS] = {oqkv0, oqkv0, oqkv0, oqkv1, oqkv1, oqkv1,
                                    oo0, oo1, ogu0, ogu0, ogu1, ogu1, od0, od1};
        const size_t lens[NJOBS] = {QN, KN, KN, QN, KN, KN, QN, QN,
                                    FN, FN, FN, FN, FN, FN};
        const int    lks [NJOBS] = {11,11,11,11,11,11,11,11, 11,11,11,11, 13,13};
        const int    rbs [NJOBS] = {0,2048,3072, 0,2048,3072, 0,0, 0,0,0,0, 0,0};
        const int    ilvs[NJOBS] = {0,0,0,0,0,0,0,0, 1,2,1,2, 0,0};
        int blk = 0;
        for (int j = 0; j < NJOBS; ++j) {
            J.src[j] = srcs[j];
            J.dst[j] = wf + offs[j];
            J.lk[j] = lks[j];
            J.rowbase[j] = rbs[j];
            J.ilv[j] = ilvs[j];
            J.startblk[j] = blk;
            blk += (int)(lens[j] / 8192);
        }
        J.startblk[NJOBS] = blk;
        cvt_f16_kernel<<<blk, 256>>>(J);
    }

    // [launch 1] pre-attn rmsnorm -> pre blocked
    {
        dim3 g(BB * T0C, 2);
        rmsnorm2_f16_kernel<<<g, 256>>>(x0, x1, pre, pa0, pa1, 0);
    }

    // [launches 2-3] QKV projection (Q half, KV half) -> qkvh linear (profiled slot)
    {
        dim3 gq(2048 / GBN, T0C / GBM, 4);
        gemm_f16<<<gq, 512, TC_SMEM_F>>>(pre, wf + oqkv0, wf + oqkv1,
                                         0, DC, 4096, 4, 0, 0, 0, 0, qkvh);
        gemm_f16<<<gq, 512, TC_SMEM_F>>>(pre, wf + oqkv0 + QHALF, wf + oqkv1 + QHALF,
                                         0, DC, 4096, 4, 0, 0, 0, 0, qkvh + 2048);
    }

    // [launch 4] RoPE + scale -> fp16 q,k,v
    rope_split_kernel<<<BB * TOTC, 256>>>(qkvh, pos, qb, kb, vb);

    // [launch 5] attention -> enc blocked
    {
        dim3 ga(TOTC / ATT_BM, NC, BB);
        attn_mma_kernel<<<ga, 256, ATT_SMEM>>>(qb, kb, vb, enc);
    }

    // [launch 6] O projection + residual (per-stream x) -> res fp32
    {
        dim3 go(DC / GBN, T0C / GBM, 4);
        gemm_f16<<<go, 512, TC_SMEM_F>>>(enc, wf + oo0, wf + oo1,
                                         res, NHC, DC, 2, x0, x1, 0, 0, 0);
    }

    // [launch 7] pre-ffw rmsnorm -> hid blocked
    {
        dim3 g(BB * T0C, 2);
        rmsnorm2_f16_kernel<<<g, 256>>>(res, res, hid, pf0, pf1, 1);
    }

    // [launch 8] fused gate-up projection (interleaved W) -> gu blocked
    {
        dim3 gf(16384 / GBN, T0C / GBM, 4);
        gemm_f16<<<gf, 512, TC_SMEM_F>>>(hid, wf + ogu0, wf + ogu1,
                                         0, DC, 16384, 3, 0, 0, 0, 0, gu);
    }

    // [launch 9] down projection + residual (concat res) -> out (stream-major)
    {
        dim3 gd(DC / GBN, T0C / GBM, 4);
        gemm_f16<<<gd, 512, TC_SMEM_F>>>(gu, wf + od0, wf + od1,
                                         out, FC, DC, 2, res, 0, 1, 1, 0);
    }
}

// round 17
// speedup vs baseline: 1.0791x; 1.0791x over previous
#include <cuda_runtime.h>
#include <cuda_fp16.h>
#include <math.h>
#include <float.h>
#include <stdint.h>

// ---------------- problem constants ----------------
#define BB   2
#define T0C  1024
#define TOTC 2048
#define DC   2048
#define NC   16
#define KC   8
#define HC   128
#define FC   8192
#define NHC  2048   // N*H
#define KHC  1024   // K*H
#define GC   2      // N/K

typedef __half fp16;

// ---------------- helpers ----------------
__device__ __forceinline__ uint32_t smem_to_u32(const void* p) {
    uint32_t a;
    asm("{ .reg .u64 t; cvta.to.shared.u64 t, %1; cvt.u32.u64 %0, t; }" : "=r"(a) : "l"(p));
    return a;
}
#define LDSM4(r, addr) \
    asm volatile("ldmatrix.sync.aligned.m8n8.x4.shared.b16 {%0,%1,%2,%3}, [%4];" \
        : "=r"((r)[0]), "=r"((r)[1]), "=r"((r)[2]), "=r"((r)[3]) : "r"(addr))
#define LDSM4T(r, addr) \
    asm volatile("ldmatrix.sync.aligned.m8n8.x4.trans.shared.b16 {%0,%1,%2,%3}, [%4];" \
        : "=r"((r)[0]), "=r"((r)[1]), "=r"((r)[2]), "=r"((r)[3]) : "r"(addr))
#define MMAF16(d, a, b0, b1) \
    asm volatile("mma.sync.aligned.m16n8k16.row.col.f32.f16.f16.f32 " \
        "{%0,%1,%2,%3},{%4,%5,%6,%7},{%8,%9},{%0,%1,%2,%3};" \
        : "+f"((d)[0]), "+f"((d)[1]), "+f"((d)[2]), "+f"((d)[3]) \
        : "r"((a)[0]), "r"((a)[1]), "r"((a)[2]), "r"((a)[3]), "r"(b0), "r"(b1))
#define CP_ASYNC16(saddr, gaddr) \
    asm volatile("cp.async.cg.shared.global [%0], [%1], 16;" :: "r"(saddr), "l"(gaddr))
#define CP_COMMIT() asm volatile("cp.async.commit_group;" ::: "memory")
#define CP_WAIT(n)  asm volatile("cp.async.wait_group %0;" :: "n"(n) : "memory")

// ---------------- scratch (device globals; no runtime alloc) ----------------
__device__ float g_res [(size_t)BB*TOTC*DC];

__device__ fp16 g_qkvh[(size_t)BB*TOTC*4096];    // packed q|k|v fp16 (pre-rope)
__device__ fp16 g_q   [(size_t)BB*TOTC*NHC];
__device__ fp16 g_k   [(size_t)BB*TOTC*KHC];
__device__ fp16 g_v   [(size_t)BB*TOTC*KHC];
__device__ fp16 g_pre [(size_t)BB*TOTC*DC];
__device__ fp16 g_enc [(size_t)BB*TOTC*NHC];
__device__ fp16 g_hid [(size_t)BB*TOTC*DC];
__device__ fp16 g_gu  [(size_t)BB*TOTC*FC];
__device__ fp16 g_wf  [125829120];  // fp16 weights: qkv0|qkv1|o0|o1|gu0(ilv)|gu1(ilv)|d0|d1

// ---------------- elementwise helpers ----------------
__device__ __forceinline__ float gelu_tanh(float x) {
    float x3 = x * x * x;
    return 0.5f * x * (1.0f + tanhf(0.7978845608028654f * (x + 0.044715f * x3)));
}
__device__ __forceinline__ uint32_t pack2h(float a, float b) {
    __half2 h = __floats2half2_rn(a, b);
    return *(uint32_t*)&h;
}

// ---------------- weight conversion: fp16 single, 14 jobs, optional row-interleave ----------------
// ilv: 0 = straight copy; 1 = write row r to row 2r (even); 2 = row r to 2r+1 (odd).
// Interleaved jobs have K = 2048 columns.
#define NJOBS 14
struct CvtF16Jobs {
    const float* src[NJOBS];
    fp16* dst[NJOBS];
    int ilv[NJOBS];
    int startblk[NJOBS + 1];
};

// 256 threads x 32 elems = 8192 elems/block
__global__ void cvt_f16_kernel(CvtF16Jobs J)
{
    int bid = blockIdx.x;
    int j = 0;
    #pragma unroll
    for (int t = 1; t < NJOBS; ++t) if (bid >= J.startblk[t]) j = t;
    int blk_off = (bid - J.startblk[j]) * 8192;
    const float* src = J.src[j];
    fp16* dst = J.dst[j];
    int ilv = J.ilv[j];

    float4 va[4][2];
    int idx[4];
    #pragma unroll
    for (int u = 0; u < 4; ++u) {
        idx[u] = blk_off + (u * 256 + threadIdx.x) * 8;
        va[u][0] = *(const float4*)(src + idx[u]);
        va[u][1] = *(const float4*)(src + idx[u] + 4);
    }
    #pragma unroll
    for (int u = 0; u < 4; ++u) {
        uint4 o;
        o.x = pack2h(va[u][0].x, va[u][0].y);
        o.y = pack2h(va[u][0].z, va[u][0].w);
        o.z = pack2h(va[u][1].x, va[u][1].y);
        o.w = pack2h(va[u][1].z, va[u][1].w);
        int didx = idx[u];
        if (ilv) {
            int row = didx >> 11, col = didx & 2047;
            didx = (((row << 1) | (ilv - 1)) << 11) | col;
        }
        *(uint4*)(dst + didx) = o;
    }
}

// ---------------- rmsnorm pair -> fp16 single ----------------
// srcmode 0: src per-stream (s0/s1, rows b*T0+t); srcmode 1: concat src s0
__global__ void rmsnorm2_f16_kernel(const float* __restrict__ s0, const float* __restrict__ s1,
                                    fp16* __restrict__ dst,
                                    const float* __restrict__ sc0, const float* __restrict__ sc1,
                                    int srcmode)
{
    int istream = blockIdx.y;
    int row = blockIdx.x;
    int b = row / T0C, t = row % T0C;
    size_t crow = (size_t)b * TOTC + (size_t)istream * T0C + t;
    const float* base = istream ? s1 : s0;
    const float* scale = istream ? sc1 : sc0;
    const float* s = srcmode ? (s0 + crow * DC) : (base + (size_t)row * DC);
    fp16* o = dst + crow * DC;

    __shared__ float red[256];
    float ss = 0.f;
    for (int d = threadIdx.x; d < DC; d += 256) { float v = s[d]; ss += v * v; }
    red[threadIdx.x] = ss;
    __syncthreads();
    for (int st = 128; st > 0; st >>= 1) {
        if (threadIdx.x < st) red[threadIdx.x] += red[threadIdx.x + st];
        __syncthreads();
    }
    float inv = rsqrtf(red[0] * (1.0f / DC) + 1e-6f);
    for (int d = threadIdx.x; d < DC; d += 256) {
        float v = s[d] * inv * (1.0f + scale[d]);
        o[d] = __float2half_rn(v);
    }
}

// ---------------- rope + convert (fp16 qkv -> fp16 q,k,v) ----------------
__global__ void rope_split_kernel(const fp16* __restrict__ qkv, const int* __restrict__ positions,
                                  fp16* __restrict__ q, fp16* __restrict__ k, fp16* __restrict__ v)
{
    int row = blockIdx.x;
    float pos = (float)positions[row];
    const float QSCALE = 0.08838834764831845f;
    const fp16* src = qkv + (size_t)row * 4096;

    __shared__ float ssn[64], scs[64];
    if (threadIdx.x < 64) {
        int j = threadIdx.x;
        float ts = powf(10000.0f, (float)j * (1.0f / 64.0f));
        float sn, cs;
        sincosf(pos / ts, &sn, &cs);
        ssn[j] = sn; scs[j] = cs;
    }
    __syncthreads();

    for (int w = threadIdx.x; w < (NC + KC) * 64; w += 256) {
        int head = w >> 6;
        int j = w & 63;
        float sn = ssn[j], cs = scs[j];
        if (head < NC) {
            float x1 = __half2float(src[head * HC + j]);
            float x2 = __half2float(src[head * HC + j + 64]);
            size_t o = ((size_t)row * NC + head) * HC;
            q[o + j]      = __float2half_rn((x1 * cs - x2 * sn) * QSCALE);
            q[o + j + 64] = __float2half_rn((x2 * cs + x1 * sn) * QSCALE);
        } else {
            int kkh = head - NC;
            float x1 = __half2float(src[2048 + kkh * HC + j]);
            float x2 = __half2float(src[2048 + kkh * HC + j + 64]);
            size_t o = ((size_t)row * KC + kkh) * HC;
            k[o + j]      = __float2half_rn(x1 * cs - x2 * sn);
            k[o + j + 64] = __float2half_rn(x2 * cs + x1 * sn);
        }
    }
    for (int idx = threadIdx.x; idx < KHC; idx += 256) {
        size_t o = (size_t)row * KHC + idx;
        v[o] = src[3072 + idx];
    }
}

// ---------------- GEMM geometry ----------------
#define GBM 256
#define GBN 128
#define GBK 32
#define GSTAGES 7
#define ROWB   80
#define TILEA_B (256 * ROWB)                 // 20480
#define TILEW_B (128 * ROWB)                 // 10240
#define STAGE_F (TILEA_B + TILEW_B)          // 30720 (fp16 single)
#define TC_SMEM_F (GSTAGES * STAGE_F)        // 215040

// ---------------- fp16 single-pass GEMM (all projections) ----------------
// A single fp16, W single fp16 per stream (W0/W1 selected by stream i).
// epi: 0 plain fp32->C, 1 gelu->C, 2 +residual->C,
//      3 fused gate-up: cols alternate (gate,up); writes gelu(g)*u fp16 -> H16 (ld FC)
//      4 plain fp16 -> H16
// resmode: 0 per-stream R (R0/R1 + b*T0*ldC), 1 concat R0 (+ arow0*ldC)
// outmode: 0 concat rows, 1 stream-major rows
__global__ __launch_bounds__(512, 1)
void gemm_f16(const fp16* __restrict__ A_,
              const fp16* __restrict__ W0, const fp16* __restrict__ W1,
              float* __restrict__ C_, int Kd, int ldC, int epi,
              const float* __restrict__ R0, const float* __restrict__ R1,
              int resmode, int outmode,
              fp16* __restrict__ H16_)
{
    extern __shared__ char smem[];
    const uint32_t s0 = smem_to_u32(smem);

    const int tid = threadIdx.x;
    const int lane = tid & 31, warp = tid >> 5;
    const int wm = warp >> 2, wn = warp & 3;      // warp tile 64(m) x 32(n)

    const int z = blockIdx.z, i = z >> 1, b = z & 1;
    const size_t arow0 = (size_t)b * TOTC + (size_t)i * T0C;
    const fp16* A = A_ + arow0 * Kd;
    const fp16* W = i ? W1 : W0;
    float* C = (outmode == 0) ? (C_ + arow0 * (size_t)ldC)
                              : (C_ + ((size_t)i * BB * T0C + (size_t)b * T0C) * (size_t)ldC);
    const float* R = 0;
    if (epi == 2) R = (resmode == 0) ? ((i ? R1 : R0) + (size_t)b * T0C * ldC)
                                     : (R0 + arow0 * (size_t)ldC);
    fp16* H16 = 0;
    if (epi == 3) H16 = H16_ + arow0 * (size_t)FC;
    else if (epi == 4) H16 = H16_ + arow0 * (size_t)ldC;

    const int m0 = blockIdx.y * GBM, n0 = blockIdx.x * GBN;
    const int nk = Kd / GBK;

    // 1536 16B chunks per stage: A 1024, W 512. 3 per thread.
    #define ISSUE_STAGE_F(cc) do {                                               \
        int kk0 = (cc) * GBK;                                                    \
        uint32_t sbase = s0 + ((cc) % GSTAGES) * STAGE_F;                        \
        _Pragma("unroll")                                                        \
        for (int it = 0; it < 3; ++it) {                                         \
            int idx = tid + it * 512;                                            \
            const fp16* gp; uint32_t sa;                                         \
            if (idx < 1024) {                                                    \
                int row = idx >> 2, ch = idx & 3;                                \
                sa = sbase + row * ROWB + ch * 16;                               \
                gp = A + (size_t)(m0 + row) * Kd + kk0 + ch * 8;                 \
            } else {                                                             \
                int cid = idx - 1024;                                            \
                int row = cid >> 2, ch = cid & 3;                                \
                sa = sbase + TILEA_B + row * ROWB + ch * 16;                     \
                gp = W + (size_t)(n0 + row) * Kd + kk0 + ch * 8;                 \
            }                                                                    \
            CP_ASYNC16(sa, gp);                                                  \
        }                                                                        \
        CP_COMMIT();                                                             \
    } while (0)

    float acc[4][4][4];
    #pragma unroll
    for (int mf = 0; mf < 4; ++mf)
        #pragma unroll
        for (int nf = 0; nf < 4; ++nf)
            #pragma unroll
            for (int r = 0; r < 4; ++r) acc[mf][nf][r] = 0.f;

    const int a_row = wm * 64 + (lane & 15);
    const int a_cj  = lane >> 4;
    const int b_row = wn * 32 + (lane & 7) + ((lane >> 4) & 1) * 8;
    const int b_cj  = (lane >> 3) & 1;

    ISSUE_STAGE_F(0);
    ISSUE_STAGE_F(1);
    ISSUE_STAGE_F(2);
    ISSUE_STAGE_F(3);
    ISSUE_STAGE_F(4);
    ISSUE_STAGE_F(5);

    for (int c = 0; c < nk; ++c) {
        if (c + 5 < nk) CP_WAIT(5); else CP_WAIT(0);
        __syncthreads();

        uint32_t sbase = s0 + (c % GSTAGES) * STAGE_F;
        uint32_t aB = sbase, bB = sbase + TILEA_B;

        #pragma unroll
        for (int ks = 0; ks < 2; ++ks) {
            uint32_t aoff = (uint32_t)(a_row * ROWB + (ks * 2 + a_cj) * 16);
            uint32_t boff = (uint32_t)(b_row * ROWB + (ks * 2 + b_cj) * 16);

            uint32_t ah[4][4], bh[2][4];
            #pragma unroll
            for (int mf = 0; mf < 4; ++mf) LDSM4(ah[mf], aB + aoff + mf * (16 * ROWB));
            #pragma unroll
            for (int nf2 = 0; nf2 < 2; ++nf2) LDSM4(bh[nf2], bB + boff + nf2 * (16 * ROWB));

            #pragma unroll
            for (int nf2 = 0; nf2 < 2; ++nf2)
                #pragma unroll
                for (int mf = 0; mf < 4; ++mf) {
                    MMAF16(acc[mf][nf2 * 2],     ah[mf], bh[nf2][0], bh[nf2][1]);
                    MMAF16(acc[mf][nf2 * 2 + 1], ah[mf], bh[nf2][2], bh[nf2][3]);
                }

            if (ks == 0 && c + 6 < nk) ISSUE_STAGE_F(c + 6);
        }
    }

    #pragma unroll
    for (int mf = 0; mf < 4; ++mf) {
        int r0 = m0 + wm * 64 + mf * 16 + (lane >> 2);
        #pragma unroll
        for (int nf = 0; nf < 4; ++nf) {
            int col = n0 + wn * 32 + nf * 8 + (lane & 3) * 2;
            float2 v0 = make_float2(acc[mf][nf][0], acc[mf][nf][1]);
            float2 v1 = make_float2(acc[mf][nf][2], acc[mf][nf][3]);
            if (epi == 3) {
                // cols alternate (gate, up): v.x = gate_j, v.y = up_j, j = col>>1
                int gcol = col >> 1;
                H16[(size_t)r0 * FC + gcol]       = __float2half_rn(gelu_tanh(v0.x) * v0.y);
                H16[(size_t)(r0 + 8) * FC + gcol] = __float2half_rn(gelu_tanh(v1.x) * v1.y);
            } else if (epi == 4) {
                *(uint32_t*)((char*)H16 + ((size_t)r0 * ldC + col) * 2)       = pack2h(v0.x, v0.y);
                *(uint32_t*)((char*)H16 + ((size_t)(r0 + 8) * ldC + col) * 2) = pack2h(v1.x, v1.y);
            } else {
                if (epi == 1) {
                    v0.x = gelu_tanh(v0.x); v0.y = gelu_tanh(v0.y);
                    v1.x = gelu_tanh(v1.x); v1.y = gelu_tanh(v1.y);
                } else if (epi == 2) {
                    float2 ra = *(const float2*)(R + (size_t)r0 * ldC + col);
                    float2 rb = *(const float2*)(R + (size_t)(r0 + 8) * ldC + col);
                    v0.x += ra.x; v0.y += ra.y;
                    v1.x += rb.x; v1.y += rb.y;
                }
                *(float2*)(C + (size_t)r0 * ldC + col)       = v0;
                *(float2*)(C + (size_t)(r0 + 8) * ldC + col) = v1;
            }
        }
    }
}

// ---------------- attention: single-fp16 flash kernel ----------------
#define ATT_BM 128
#define ATT_BN 32
#define QROWB 272
#define KROWB 272
#define PROWB 80
#define SQ 0
#define SKV 34816
#define KVTILE 8704
#define SP 69632
#define ATT_SMEM 79872
#define NEGA (-1e30f)

__global__ __launch_bounds__(256, 1)
void attn_mma_kernel(const fp16* __restrict__ q, const fp16* __restrict__ k,
                     const fp16* __restrict__ v, fp16* __restrict__ enc)
{
    extern __shared__ char smem[];
    const uint32_t s0u = smem_to_u32(smem);
    const int tid = threadIdx.x, lane = tid & 31, w = tid >> 5;
    const int bq = blockIdx.z;
    const int n = blockIdx.y;
    const int kk = n >> 1;
    const int t0 = ((int)gridDim.x - 1 - (int)blockIdx.x) * ATT_BM;
    const size_t bT = (size_t)bq * TOTC;

    // Q tile: 128 rows x 128 fp16 = 2048 16B chunks
    #pragma unroll
    for (int it = 0; it < 8; ++it) {
        int idx = tid + it * 256;
        int row = idx >> 4, ch = idx & 15;
        const fp16* src = q + ((bT + t0 + row) * NC + n) * HC + ch * 8;
        CP_ASYNC16(s0u + SQ + row * QROWB + ch * 16, src);
    }
    CP_COMMIT();

    #define LOAD_KV(j) do {                                                        \
        int _bf = (j) & 1; int _s0 = (j) * ATT_BN;                                 \
        _Pragma("unroll")                                                          \
        for (int it = 0; it < 4; ++it) {                                           \
            int idx = tid + it * 256;                                              \
            int tt = idx >> 9, cid = idx & 511, row = cid >> 4, ch = cid & 15;     \
            const fp16* srcp = (tt ? v : k) + ((bT + _s0 + row) * KC + kk) * HC + ch * 8; \
            CP_ASYNC16(s0u + SKV + (_bf * 2 + tt) * KVTILE + row * KROWB + ch * 16, srcp); \
        }                                                                          \
        CP_COMMIT();                                                               \
    } while (0)

    const int nb = t0 / ATT_BN + 4;
    LOAD_KV(0);

    const int tw = t0 + w * 16;
    const int r0 = lane >> 2;
    float oacc[16][4];
    #pragma unroll
    for (int a = 0; a < 16; ++a) { oacc[a][0] = oacc[a][1] = oacc[a][2] = oacc[a][3] = 0.f; }
    float mrow0 = NEGA, mrow1 = NEGA, lrow0 = 0.f, lrow1 = 0.f;

    const uint32_t ps_base = s0u + SP + (w * 16) * PROWB;

    for (int j = 0; j < nb; ++j) {
        CP_WAIT(0);
        __syncthreads();
        if (j + 1 < nb) LOAD_KV(j + 1);

        const int sblk = j * ATT_BN;
        const int bf = j & 1;
        const uint32_t kB = s0u + SKV + (bf * 2 + 0) * KVTILE;
        const uint32_t vB = s0u + SKV + (bf * 2 + 1) * KVTILE;

        if (sblk <= tw + 15) {
            float sacc[4][4];
            #pragma unroll
            for (int nf = 0; nf < 4; ++nf) { sacc[nf][0]=sacc[nf][1]=sacc[nf][2]=sacc[nf][3]=0.f; }
            const uint32_t aoff_base = (uint32_t)((w * 16 + (lane & 15)) * QROWB + (lane >> 4) * 16);
            const uint32_t brow = (uint32_t)((lane & 7) + ((lane >> 4) & 1) * 8);
            const uint32_t bco  = (uint32_t)(((lane >> 3) & 1) * 16);
            #pragma unroll
            for (int ks = 0; ks < 8; ++ks) {
                uint32_t ah[4], bh0[4], bh1[4];
                uint32_t aoff = aoff_base + ks * 32;
                LDSM4(ah, s0u + SQ + aoff);
                uint32_t boff0 = brow * KROWB + ks * 32 + bco;
                uint32_t boff1 = boff0 + 16 * KROWB;
                LDSM4(bh0, kB + boff0); LDSM4(bh1, kB + boff1);
                MMAF16(sacc[0], ah, bh0[0], bh0[1]);
                MMAF16(sacc[1], ah, bh0[2], bh0[3]);
                MMAF16(sacc[2], ah, bh1[0], bh1[1]);
                MMAF16(sacc[3], ah, bh1[2], bh1[3]);
            }

            if (sblk + ATT_BN - 1 > tw) {
                #pragma unroll
                for (int nf = 0; nf < 4; ++nf) {
                    int sg = sblk + nf * 8 + (lane & 3) * 2;
                    int tg0 = tw + r0, tg1 = tg0 + 8;
                    if (sg     > tg0) sacc[nf][0] = NEGA;
                    if (sg + 1 > tg0) sacc[nf][1] = NEGA;
                    if (sg     > tg1) sacc[nf][2] = NEGA;
                    if (sg + 1 > tg1) sacc[nf][3] = NEGA;
                }
            }

            float mx0 = NEGA, mx1 = NEGA;
            #pragma unroll
            for (int nf = 0; nf < 4; ++nf) {
                mx0 = fmaxf(mx0, fmaxf(sacc[nf][0], sacc[nf][1]));
                mx1 = fmaxf(mx1, fmaxf(sacc[nf][2], sacc[nf][3]));
            }
            mx0 = fmaxf(mx0, __shfl_xor_sync(0xffffffffu, mx0, 1));
            mx0 = fmaxf(mx0, __shfl_xor_sync(0xffffffffu, mx0, 2));
            mx1 = fmaxf(mx1, __shfl_xor_sync(0xffffffffu, mx1, 1));
            mx1 = fmaxf(mx1, __shfl_xor_sync(0xffffffffu, mx1, 2));
            float mn0 = fmaxf(mrow0, mx0), mn1 = fmaxf(mrow1, mx1);
            float al0 = __expf(mrow0 - mn0), al1 = __expf(mrow1 - mn1);
            float se0 = 0.f, se1 = 0.f;
            #pragma unroll
            for (int nf = 0; nf < 4; ++nf) {
                float p0 = __expf(sacc[nf][0] - mn0);
                float p1 = __expf(sacc[nf][1] - mn0);
                float p2 = __expf(sacc[nf][2] - mn1);
                float p3 = __expf(sacc[nf][3] - mn1);
                se0 += p0 + p1; se1 += p2 + p3;
                uint32_t pcol = (uint32_t)((nf * 8 + (lane & 3) * 2) * 2);
                *(uint32_t*)(smem + (ps_base - s0u) + r0 * PROWB + pcol)       = pack2h(p0, p1);
                *(uint32_t*)(smem + (ps_base - s0u) + (r0 + 8) * PROWB + pcol) = pack2h(p2, p3);
            }
            se0 += __shfl_xor_sync(0xffffffffu, se0, 1);
            se0 += __shfl_xor_sync(0xffffffffu, se0, 2);
            se1 += __shfl_xor_sync(0xffffffffu, se1, 1);
            se1 += __shfl_xor_sync(0xffffffffu, se1, 2);
            mrow0 = mn0; mrow1 = mn1;
            lrow0 = lrow0 * al0 + se0;
            lrow1 = lrow1 * al1 + se1;
            #pragma unroll
            for (int a = 0; a < 16; ++a) {
                oacc[a][0] *= al0; oacc[a][1] *= al0;
                oacc[a][2] *= al1; oacc[a][3] *= al1;
            }
            __syncwarp();

            const uint32_t vrow = (uint32_t)((lane & 7) + ((lane >> 3) & 1) * 8);
            const uint32_t vco  = (uint32_t)((lane >> 4) * 16);
            #pragma unroll
            for (int ks2 = 0; ks2 < 2; ++ks2) {
                uint32_t ph[4];
                uint32_t pa = (uint32_t)((lane & 15) * PROWB + (ks2 * 16 + (lane >> 4) * 8) * 2);
                LDSM4(ph, ps_base + pa);
                #pragma unroll
                for (int hf = 0; hf < 8; ++hf) {
                    uint32_t bvh[4];
                    uint32_t voff = (ks2 * 16 + vrow) * KROWB + hf * 32 + vco;
                    LDSM4T(bvh, vB + voff);
                    MMAF16(oacc[2*hf],     ph, bvh[0], bvh[1]);
                    MMAF16(oacc[2*hf + 1], ph, bvh[2], bvh[3]);
                }
            }
        }
    }

    float inv0 = 1.0f / lrow0, inv1 = 1.0f / lrow1;
    #pragma unroll
    for (int nt = 0; nt < 16; ++nt) {
        int hcol = nt * 8 + (lane & 3) * 2;
        size_t o0 = ((bT + tw + r0) * NC + n) * HC + hcol;
        size_t o1 = ((bT + tw + r0 + 8) * NC + n) * HC + hcol;
        *(uint32_t*)((char*)enc + o0 * 2) = pack2h(oacc[nt][0] * inv0, oacc[nt][1] * inv0);
        *(uint32_t*)((char*)enc + o1 * 2) = pack2h(oacc[nt][2] * inv1, oacc[nt][3] * inv1);
    }
}

// ---------------- host ----------------
extern "C" void kernel_launch(void* const* d_in, const int* in_sizes, int n_in,
                              void* d_out, int out_size)
{
    (void)in_sizes; (void)n_in; (void)out_size;
    const float* x0  = (const float*)d_in[0];
    const float* x1  = (const float*)d_in[1];
    const int*   pos = (const int*)  d_in[2];
    const float* q0w = (const float*)d_in[4];
    const float* q1w = (const float*)d_in[5];
    const float* k0w = (const float*)d_in[6];
    const float* k1w = (const float*)d_in[7];
    const float* v0w = (const float*)d_in[8];
    const float* v1w = (const float*)d_in[9];
    const float* o0w = (const float*)d_in[10];
    const float* o1w = (const float*)d_in[11];
    const float* gt0 = (const float*)d_in[12];
    const float* gt1 = (const float*)d_in[13];
    const float* up0 = (const float*)d_in[14];
    const float* up1 = (const float*)d_in[15];
    const float* dw0 = (const float*)d_in[16];
    const float* dw1 = (const float*)d_in[17];
    const float* pa0 = (const float*)d_in[18];
    const float* pa1 = (const float*)d_in[19];
    const float* pf0 = (const float*)d_in[20];
    const float* pf1 = (const float*)d_in[21];
    float* out = (float*)d_out;

    float *res;
    fp16 *qkvh, *qb, *kb, *vb, *pre, *enc, *hid, *gu, *wf;
    cudaGetSymbolAddress((void**)&res,  g_res);
    cudaGetSymbolAddress((void**)&qkvh, g_qkvh);
    cudaGetSymbolAddress((void**)&qb,   g_q);
    cudaGetSymbolAddress((void**)&kb,   g_k);
    cudaGetSymbolAddress((void**)&vb,   g_v);
    cudaGetSymbolAddress((void**)&pre,  g_pre);
    cudaGetSymbolAddress((void**)&enc,  g_enc);
    cudaGetSymbolAddress((void**)&hid,  g_hid);
    cudaGetSymbolAddress((void**)&gu,   g_gu);
    cudaGetSymbolAddress((void**)&wf,   g_wf);

    cudaFuncSetAttribute(gemm_f16, cudaFuncAttributeMaxDynamicSharedMemorySize, TC_SMEM_F);
    cudaFuncSetAttribute(attn_mma_kernel, cudaFuncAttributeMaxDynamicSharedMemorySize, ATT_SMEM);

    const size_t QN   = (size_t)NHC * DC;     // 4194304
    const size_t KN   = (size_t)KHC * DC;     // 2097152
    const size_t FN   = (size_t)FC * DC;      // 16777216
    const size_t QKVN = QN + 2 * KN;          // 8388608
    const size_t oqkv0 = 0, oqkv1 = QKVN;
    const size_t oo0  = 2 * QKVN,   oo1  = oo0 + QN;
    const size_t ogu0 = oo1 + QN,   ogu1 = ogu0 + 2 * FN;   // interleaved gate|up
    const size_t od0  = ogu1 + 2 * FN, od1 = od0 + FN;

    // [launch 0] all weight conversions -> fp16 (gate/up row-interleaved)
    {
        CvtF16Jobs J;
        const float* srcs[NJOBS] = {q0w, k0w, v0w, q1w, k1w, v1w, o0w, o1w,
                                    gt0, up0, gt1, up1, dw0, dw1};
        const size_t offs[NJOBS] = {oqkv0, oqkv0 + QN, oqkv0 + QN + KN,
                                    oqkv1, oqkv1 + QN, oqkv1 + QN + KN,
                                    oo0, oo1, ogu0, ogu0, ogu1, ogu1, od0, od1};
        const size_t lens[NJOBS] = {QN, KN, KN, QN, KN, KN, QN, QN,
                                    FN, FN, FN, FN, FN, FN};
        const int    ilvs[NJOBS] = {0,0,0,0,0,0,0,0, 1,2,1,2, 0,0};
        int blk = 0;
        for (int j = 0; j < NJOBS; ++j) {
            J.src[j] = srcs[j];
            J.dst[j] = wf + offs[j];
            J.ilv[j] = ilvs[j];
            J.startblk[j] = blk;
            blk += (int)(lens[j] / 8192);
        }
        J.startblk[NJOBS] = blk;
        cvt_f16_kernel<<<blk, 256>>>(J);
    }

    // [launch 1] pre-attn rmsnorm -> fp16
    {
        dim3 g(BB * T0C, 2);
        rmsnorm2_f16_kernel<<<g, 256>>>(x0, x1, pre, pa0, pa1, 0);
    }

    // [launches 2-3] QKV projection (Q half, KV half) -> fp16 qkvh (profiled slot)
    {
        dim3 gq(2048 / GBN, T0C / GBM, 4);
        gemm_f16<<<gq, 512, TC_SMEM_F>>>(pre, wf + oqkv0, wf + oqkv1,
                                         0, DC, 4096, 4, 0, 0, 0, 0, qkvh);
        gemm_f16<<<gq, 512, TC_SMEM_F>>>(pre, wf + oqkv0 + QN, wf + oqkv1 + QN,
                                         0, DC, 4096, 4, 0, 0, 0, 0, qkvh + 2048);
    }

    // [launch 4] RoPE + scale -> fp16 q,k,v
    rope_split_kernel<<<BB * TOTC, 256>>>(qkvh, pos, qb, kb, vb);

    // [launch 5] attention -> fp16 enc
    {
        dim3 ga(TOTC / ATT_BM, NC, BB);
        attn_mma_kernel<<<ga, 256, ATT_SMEM>>>(qb, kb, vb, enc);
    }

    // [launch 6] O projection + residual (per-stream x) -> fp32 res
    {
        dim3 go(DC / GBN, T0C / GBM, 4);
        gemm_f16<<<go, 512, TC_SMEM_F>>>(enc, wf + oo0, wf + oo1,
                                         res, NHC, DC, 2, x0, x1, 0, 0, 0);
    }

    // [launch 7] pre-ffw rmsnorm -> fp16 (concat src)
    {
        dim3 g(BB * T0C, 2);
        rmsnorm2_f16_kernel<<<g, 256>>>(res, res, hid, pf0, pf1, 1);
    }

    // [launch 8] fused gate-up projection (interleaved W) -> gu fp16
    {
        dim3 gf(16384 / GBN, T0C / GBM, 4);
        gemm_f16<<<gf, 512, TC_SMEM_F>>>(hid, wf + ogu0, wf + ogu1,
                                         0, DC, 16384, 3, 0, 0, 0, 0, gu);
    }

    // [launch 9] down projection + residual (concat res) -> out (stream-major)
    {
        dim3 gd(DC / GBN, T0C / GBM, 4);
        gemm_f16<<<gd, 512, TC_SMEM_F>>>(gu, wf + od0, wf + od1,
                                         out, FC, DC, 2, res, 0, 1, 1, 0);
    }
}